// round 10
// baseline (speedup 1.0000x reference)
#include <cuda_runtime.h>
#include <cuda_fp16.h>
#include <cstdint>

#define N_NODES 100000
#define N_EDGES 1600000
#define HID 128

// ---------------- device scratch ----------------
__device__ int g_deg[N_NODES];
__device__ int g_off[N_NODES];
__device__ int g_cur[N_NODES];
__device__ int g_bsum[128];
__device__ int g_csr[N_EDGES];
__device__ int g_e32;
__device__ float  g_agg[(size_t)N_NODES * HID];  // gather output (tf32-rounded)
__device__ float  g_h[(size_t)N_NODES * HID];    // hidden (tf32-rounded)
__device__ __half g_xh[(size_t)N_NODES * HID];   // fp16 mirror of current x

__device__ __forceinline__ float tf32r(float x) {
    float y;
    asm("cvt.rna.tf32.f32 %0, %1;" : "=f"(y) : "f"(x));
    return y;
}
__device__ __forceinline__ float4 h4f(uint2 u) {
    __half2 h0 = *(__half2*)&u.x;
    __half2 h1 = *(__half2*)&u.y;
    float2 f0 = __half22float2(h0);
    float2 f1 = __half22float2(h1);
    return make_float4(f0.x, f0.y, f1.x, f1.y);
}

// ---------------- edge dtype detection ----------------
__global__ void detect_k(const void* __restrict__ ei) {
    if (threadIdx.x == 0 && blockIdx.x == 0) {
        const long long* p = (const long long*)ei;
        int e32 = 0;
        for (int i = 0; i < 16; i++) {
            long long v = p[i];
            if (v < 0 || v >= N_NODES) { e32 = 1; break; }
        }
        g_e32 = e32;
    }
}
__device__ __forceinline__ int edge_at(const void* ei, long long idx) {
    if (g_e32) return ((const int*)ei)[idx];
    return (int)((const long long*)ei)[idx];
}

// ---------------- CSR build ----------------
__global__ void zero_deg_k() {
    int i = blockIdx.x * blockDim.x + threadIdx.x;
    if (i < N_NODES) g_deg[i] = 0;
}
__global__ void count_k(const void* __restrict__ ei) {
    int e = blockIdx.x * blockDim.x + threadIdx.x;
    if (e < N_EDGES) {
        int d = edge_at(ei, (long long)N_EDGES + e);
        if (d >= 0 && d < N_NODES) atomicAdd(&g_deg[d], 1);
    }
}
__global__ void scan1_k() {
    __shared__ int s[1024];
    int t = threadIdx.x;
    int i = blockIdx.x * 1024 + t;
    int v = (i < N_NODES) ? g_deg[i] : 0;
    s[t] = v;
    __syncthreads();
    for (int o = 1; o < 1024; o <<= 1) {
        int x = (t >= o) ? s[t - o] : 0;
        __syncthreads();
        s[t] += x;
        __syncthreads();
    }
    if (i < N_NODES) g_off[i] = s[t] - v;
    if (t == 1023) g_bsum[blockIdx.x] = s[1023];
}
__global__ void scan2_k(int nb) {
    __shared__ int s[128];
    int t = threadIdx.x;
    int v = (t < nb) ? g_bsum[t] : 0;
    s[t] = v;
    __syncthreads();
    for (int o = 1; o < 128; o <<= 1) {
        int x = (t >= o) ? s[t - o] : 0;
        __syncthreads();
        s[t] += x;
        __syncthreads();
    }
    if (t < nb) g_bsum[t] = s[t] - v;
}
__global__ void scan3_k() {
    int i = blockIdx.x * blockDim.x + threadIdx.x;
    if (i < N_NODES) {
        int o = g_off[i] + g_bsum[i >> 10];
        g_off[i] = o;
        g_cur[i] = o;
    }
}
__global__ void fill_k(const void* __restrict__ ei) {
    int e = blockIdx.x * blockDim.x + threadIdx.x;
    if (e < N_EDGES) {
        int d = edge_at(ei, (long long)N_EDGES + e);
        int s = edge_at(ei, e);
        if (d < 0 || d >= N_NODES) return;
        if (s < 0) s = 0;
        if (s >= N_NODES) s = N_NODES - 1;
        int p = atomicAdd(&g_cur[d], 1);
        if (p >= 0 && p < N_EDGES) g_csr[p] = s;
    }
}

// ---------------- fp16 mirror init ----------------
__global__ void tohalf_k(const float* __restrict__ x) {
    int i = blockIdx.x * blockDim.x + threadIdx.x;   // float4 index
    if (i < N_NODES * 32) {
        float4 v = ((const float4*)x)[i];
        __half2 h0 = __floats2half2_rn(v.x, v.y);
        __half2 h1 = __floats2half2_rn(v.z, v.w);
        uint2 u;
        u.x = *(uint32_t*)&h0;
        u.y = *(uint32_t*)&h1;
        ((uint2*)g_xh)[i] = u;
    }
}

// ---------------- aggregation: fp16 rows, fp32 accumulate ----------------
// g_agg[i] = tf32( xh[i] + sum_{j in N(i)} xh[j] )
__global__ void gather_k() {
    int w = (blockIdx.x * blockDim.x + threadIdx.x) >> 5;
    int lane = threadIdx.x & 31;
    if (w >= N_NODES) return;
    const uint2* __restrict__ X = (const uint2*)g_xh;  // 4 halves per uint2; 32/row
    float4 a = h4f(__ldg(&X[(size_t)w * 32 + lane]));
    int s = g_off[w];
    int e = s + g_deg[w];
    int k = s;
    for (; k + 8 <= e; k += 8) {
        int j0 = __ldg(&g_csr[k + 0]);
        int j1 = __ldg(&g_csr[k + 1]);
        int j2 = __ldg(&g_csr[k + 2]);
        int j3 = __ldg(&g_csr[k + 3]);
        int j4 = __ldg(&g_csr[k + 4]);
        int j5 = __ldg(&g_csr[k + 5]);
        int j6 = __ldg(&g_csr[k + 6]);
        int j7 = __ldg(&g_csr[k + 7]);
        float4 v0 = h4f(__ldg(&X[(size_t)j0 * 32 + lane]));
        float4 v1 = h4f(__ldg(&X[(size_t)j1 * 32 + lane]));
        float4 v2 = h4f(__ldg(&X[(size_t)j2 * 32 + lane]));
        float4 v3 = h4f(__ldg(&X[(size_t)j3 * 32 + lane]));
        float4 v4 = h4f(__ldg(&X[(size_t)j4 * 32 + lane]));
        float4 v5 = h4f(__ldg(&X[(size_t)j5 * 32 + lane]));
        float4 v6 = h4f(__ldg(&X[(size_t)j6 * 32 + lane]));
        float4 v7 = h4f(__ldg(&X[(size_t)j7 * 32 + lane]));
        a.x += ((v0.x + v1.x) + (v2.x + v3.x)) + ((v4.x + v5.x) + (v6.x + v7.x));
        a.y += ((v0.y + v1.y) + (v2.y + v3.y)) + ((v4.y + v5.y) + (v6.y + v7.y));
        a.z += ((v0.z + v1.z) + (v2.z + v3.z)) + ((v4.z + v5.z) + (v6.z + v7.z));
        a.w += ((v0.w + v1.w) + (v2.w + v3.w)) + ((v4.w + v5.w) + (v6.w + v7.w));
    }
    for (; k < e; k++) {
        int j = __ldg(&g_csr[k]);
        float4 v = h4f(__ldg(&X[(size_t)j * 32 + lane]));
        a.x += v.x; a.y += v.y; a.z += v.z; a.w += v.w;
    }
    a.x = tf32r(a.x); a.y = tf32r(a.y); a.z = tf32r(a.z); a.w = tf32r(a.w);
    ((float4*)g_agg)[(size_t)w * 32 + lane] = a;
}

// ---------------- GEMM kernel (mma.sync tf32), 64-row tiles, 2 CTA/SM ----------------
// mode 0: g_h = tf32(relu(g_agg @ W + bias))
// mode 1: out = resid + relu(g_h @ W + bias);  also writes fp16 mirror g_xh
#define SA_STRIDE 132
#define SW_STRIDE 136
#define SM_B 0
#define SM_A 128
#define SM_W (SM_A + 64 * SA_STRIDE)
#define SMEM_FLOATS (SM_W + 128 * SW_STRIDE)   // 25984 floats = 103936 B

__device__ __forceinline__ void mma8(float* d, const uint32_t* a, const uint32_t* b) {
    asm volatile(
        "mma.sync.aligned.m16n8k8.row.col.f32.tf32.tf32.f32 "
        "{%0,%1,%2,%3}, {%4,%5,%6,%7}, {%8,%9}, {%0,%1,%2,%3};\n"
        : "+f"(d[0]), "+f"(d[1]), "+f"(d[2]), "+f"(d[3])
        : "r"(a[0]), "r"(a[1]), "r"(a[2]), "r"(a[3]), "r"(b[0]), "r"(b[1]));
}

__global__ __launch_bounds__(256, 2)
void gemm_k(const float* __restrict__ W, const float* __restrict__ bias,
            const float* __restrict__ resid, float* __restrict__ out_arg,
            int mode)
{
    const float* __restrict__ A = (mode == 0) ? g_agg : g_h;
    float* __restrict__ out     = (mode == 0) ? g_h   : out_arg;

    extern __shared__ float sm[];
    int tid = threadIdx.x, wid = tid >> 5, lane = tid & 31;
    int bm = blockIdx.x * 64;

    if (tid < 128) sm[SM_B + tid] = bias[tid];

    // ---- load W tile (128 x 128, tf32-rounded) ----
#pragma unroll
    for (int it = 0; it < 16; it++) {
        int idx4 = it * 256 + tid;
        int row = idx4 >> 5;
        int c4  = (idx4 & 31) * 4;
        float4 w = *(const float4*)(W + (size_t)row * 128 + c4);
        float* q = &sm[SM_W + row * SW_STRIDE + c4];
        q[0] = tf32r(w.x); q[1] = tf32r(w.y); q[2] = tf32r(w.z); q[3] = tf32r(w.w);
    }
    // ---- load A tile (64 x 128, already tf32-rounded in gmem) ----
#pragma unroll
    for (int it = 0; it < 8; it++) {
        int idx4 = it * 256 + tid;
        int row = idx4 >> 5;
        int c4  = (idx4 & 31) * 4;
        float4 v = make_float4(0.f, 0.f, 0.f, 0.f);
        if (bm + row < N_NODES)
            v = *(const float4*)(A + (size_t)(bm + row) * 128 + c4);
        float* p = &sm[SM_A + row * SA_STRIDE + c4];
        p[0] = v.x; p[1] = v.y; p[2] = v.z; p[3] = v.w;
    }
    __syncthreads();

    int m_base = (wid & 1) * 32;
    int n_base = (wid >> 1) * 32;
    int qr = lane >> 2;
    int qc = lane & 3;

    float acc[2][4][4];
#pragma unroll
    for (int mt = 0; mt < 2; mt++)
#pragma unroll
        for (int nt = 0; nt < 4; nt++)
#pragma unroll
            for (int j = 0; j < 4; j++) acc[mt][nt][j] = 0.f;

#pragma unroll
    for (int ks = 0; ks < 16; ks++) {
        int k = ks * 8;
        uint32_t afr[2][4];
#pragma unroll
        for (int mt = 0; mt < 2; mt++) {
            const float* ar = &sm[SM_A + (m_base + mt * 16 + qr) * SA_STRIDE + k + qc];
            afr[mt][0] = __float_as_uint(ar[0]);
            afr[mt][1] = __float_as_uint(ar[8 * SA_STRIDE]);
            afr[mt][2] = __float_as_uint(ar[4]);
            afr[mt][3] = __float_as_uint(ar[8 * SA_STRIDE + 4]);
        }
        uint32_t bfr[4][2];
#pragma unroll
        for (int nt = 0; nt < 4; nt++) {
            const float* br = &sm[SM_W + (k + qc) * SW_STRIDE + n_base + nt * 8 + qr];
            bfr[nt][0] = __float_as_uint(br[0]);
            bfr[nt][1] = __float_as_uint(br[4 * SW_STRIDE]);
        }
#pragma unroll
        for (int mt = 0; mt < 2; mt++)
#pragma unroll
            for (int nt = 0; nt < 4; nt++)
                mma8(acc[mt][nt], afr[mt], bfr[nt]);
    }

    // ---- epilogue ----
    if (mode == 0) {
#pragma unroll
        for (int mt = 0; mt < 2; mt++) {
#pragma unroll
            for (int half = 0; half < 2; half++) {
                int r = bm + m_base + mt * 16 + qr + half * 8;
                if (r >= N_NODES) continue;
#pragma unroll
                for (int nt = 0; nt < 4; nt++) {
                    int c = n_base + nt * 8 + qc * 2;
                    float2 o;
                    o.x = tf32r(fmaxf(acc[mt][nt][half * 2 + 0] + sm[SM_B + c], 0.f));
                    o.y = tf32r(fmaxf(acc[mt][nt][half * 2 + 1] + sm[SM_B + c + 1], 0.f));
                    *(float2*)(out + (size_t)r * 128 + c) = o;
                }
            }
        }
    } else {
#pragma unroll
        for (int mt = 0; mt < 2; mt++) {
#pragma unroll
            for (int half = 0; half < 2; half++) {
                int r = bm + m_base + mt * 16 + qr + half * 8;
                if (r >= N_NODES) continue;
#pragma unroll
                for (int nt = 0; nt < 4; nt++) {
                    int c = n_base + nt * 8 + qc * 2;
                    float2 rv = *(const float2*)(resid + (size_t)r * 128 + c);
                    float2 o;
                    o.x = rv.x + fmaxf(acc[mt][nt][half * 2 + 0] + sm[SM_B + c], 0.f);
                    o.y = rv.y + fmaxf(acc[mt][nt][half * 2 + 1] + sm[SM_B + c + 1], 0.f);
                    *(float2*)(out + (size_t)r * 128 + c) = o;
                    // fp16 mirror for next layer's gather
                    __half2 hh = __floats2half2_rn(o.x, o.y);
                    *(__half2*)(&g_xh[(size_t)r * 128 + c]) = hh;
                }
            }
        }
    }
}

// ---------------- launch ----------------
extern "C" void kernel_launch(void* const* d_in, const int* in_sizes, int n_in,
                              void* d_out, int out_size) {
    const float* x0  = (const float*)d_in[0];
    const void*  ei  = d_in[1];
    const float* W1  = (const float*)d_in[2];
    const float* b1  = (const float*)d_in[3];
    const float* W2  = (const float*)d_in[4];
    const float* b2  = (const float*)d_in[5];
    float*       xout = (float*)d_out;

    static int smem_set = 0;
    if (!smem_set) {
        cudaFuncSetAttribute(gemm_k, cudaFuncAttributeMaxDynamicSharedMemorySize,
                             SMEM_FLOATS * 4);
        smem_set = 1;
    }

    detect_k<<<1, 32>>>(ei);
    zero_deg_k<<<(N_NODES + 255) / 256, 256>>>();
    count_k<<<(N_EDGES + 255) / 256, 256>>>(ei);
    int nb = (N_NODES + 1023) / 1024;
    scan1_k<<<nb, 1024>>>();
    scan2_k<<<1, 128>>>(nb);
    scan3_k<<<(N_NODES + 255) / 256, 256>>>();
    fill_k<<<(N_EDGES + 255) / 256, 256>>>(ei);
    tohalf_k<<<(N_NODES * 32 + 255) / 256, 256>>>(x0);   // fp16 mirror of x0

    int ggrid = (N_NODES + 63) / 64;     // 1563
    for (int l = 0; l < 4; l++) {
        const float* xin = (l == 0) ? x0 : xout;
        gather_k<<<(N_NODES + 7) / 8, 256>>>();
        gemm_k<<<ggrid, 256, SMEM_FLOATS * 4>>>(
            W1 + (size_t)l * HID * HID, b1 + (size_t)l * HID,
            nullptr, nullptr, 0);
        gemm_k<<<ggrid, 256, SMEM_FLOATS * 4>>>(
            W2 + (size_t)l * HID * HID, b2 + (size_t)l * HID,
            xin, xout, 1);
    }
}

// round 11
// speedup vs baseline: 1.3134x; 1.3134x over previous
#include <cuda_runtime.h>
#include <cuda_fp16.h>
#include <cstdint>

#define N_NODES 100000
#define N_EDGES 1600000
#define HID 128

// ---------------- device scratch ----------------
__device__ int g_deg[N_NODES];
__device__ int g_off[N_NODES];
__device__ int g_cur[N_NODES];
__device__ int g_bsum[128];
__device__ int g_csr[N_EDGES];
__device__ int g_e32;
__device__ __half g_agg[(size_t)N_NODES * HID];  // gather output (fp16)
__device__ __half g_h[(size_t)N_NODES * HID];    // hidden (fp16)
__device__ __half g_xh[(size_t)N_NODES * HID];   // fp16 mirror of current x
__device__ __half g_wh[8 * 128 * 128];           // fp16 TRANSPOSED weights Wt[n][k]

__device__ __forceinline__ float4 h4f(uint2 u) {
    __half2 h0 = *(__half2*)&u.x;
    __half2 h1 = *(__half2*)&u.y;
    float2 f0 = __half22float2(h0);
    float2 f1 = __half22float2(h1);
    return make_float4(f0.x, f0.y, f1.x, f1.y);
}

// ---------------- edge dtype detection ----------------
__global__ void detect_k(const void* __restrict__ ei) {
    if (threadIdx.x == 0 && blockIdx.x == 0) {
        const long long* p = (const long long*)ei;
        int e32 = 0;
        for (int i = 0; i < 16; i++) {
            long long v = p[i];
            if (v < 0 || v >= N_NODES) { e32 = 1; break; }
        }
        g_e32 = e32;
    }
}
__device__ __forceinline__ int edge_at(const void* ei, long long idx) {
    if (g_e32) return ((const int*)ei)[idx];
    return (int)((const long long*)ei)[idx];
}

// ---------------- CSR build ----------------
__global__ void zero_deg_k() {
    int i = blockIdx.x * blockDim.x + threadIdx.x;
    if (i < N_NODES) g_deg[i] = 0;
}
__global__ void count_k(const void* __restrict__ ei) {
    int e = blockIdx.x * blockDim.x + threadIdx.x;
    if (e < N_EDGES) {
        int d = edge_at(ei, (long long)N_EDGES + e);
        if (d >= 0 && d < N_NODES) atomicAdd(&g_deg[d], 1);
    }
}
__global__ void scan1_k() {
    __shared__ int s[1024];
    int t = threadIdx.x;
    int i = blockIdx.x * 1024 + t;
    int v = (i < N_NODES) ? g_deg[i] : 0;
    s[t] = v;
    __syncthreads();
    for (int o = 1; o < 1024; o <<= 1) {
        int x = (t >= o) ? s[t - o] : 0;
        __syncthreads();
        s[t] += x;
        __syncthreads();
    }
    if (i < N_NODES) g_off[i] = s[t] - v;
    if (t == 1023) g_bsum[blockIdx.x] = s[1023];
}
__global__ void scan2_k(int nb) {
    __shared__ int s[128];
    int t = threadIdx.x;
    int v = (t < nb) ? g_bsum[t] : 0;
    s[t] = v;
    __syncthreads();
    for (int o = 1; o < 128; o <<= 1) {
        int x = (t >= o) ? s[t - o] : 0;
        __syncthreads();
        s[t] += x;
        __syncthreads();
    }
    if (t < nb) g_bsum[t] = s[t] - v;
}
__global__ void scan3_k() {
    int i = blockIdx.x * blockDim.x + threadIdx.x;
    if (i < N_NODES) {
        int o = g_off[i] + g_bsum[i >> 10];
        g_off[i] = o;
        g_cur[i] = o;
    }
}
__global__ void fill_k(const void* __restrict__ ei) {
    int e = blockIdx.x * blockDim.x + threadIdx.x;
    if (e < N_EDGES) {
        int d = edge_at(ei, (long long)N_EDGES + e);
        int s = edge_at(ei, e);
        if (d < 0 || d >= N_NODES) return;
        if (s < 0) s = 0;
        if (s >= N_NODES) s = N_NODES - 1;
        int p = atomicAdd(&g_cur[d], 1);
        if (p >= 0 && p < N_EDGES) g_csr[p] = s;
    }
}

// ---------------- one-time converts ----------------
__global__ void tohalf_k(const float* __restrict__ x) {
    int i = blockIdx.x * blockDim.x + threadIdx.x;   // float4 index
    if (i < N_NODES * 32) {
        float4 v = ((const float4*)x)[i];
        __half2 h0 = __floats2half2_rn(v.x, v.y);
        __half2 h1 = __floats2half2_rn(v.z, v.w);
        uint2 u;
        u.x = *(uint32_t*)&h0;
        u.y = *(uint32_t*)&h1;
        ((uint2*)g_xh)[i] = u;
    }
}

// convert + transpose all 8 weight matrices: g_wh[m][n][k] = fp16(W[m][k][n])
__global__ void convw_k(const float* __restrict__ W1, const float* __restrict__ W2) {
    int i = blockIdx.x * blockDim.x + threadIdx.x;   // 8*128*32
    if (i >= 8 * 128 * 32) return;
    int n4 = (i & 31) * 4;
    int k  = (i >> 5) & 127;
    int m  = i >> 12;
    const float* W = (m < 4) ? (W1 + (size_t)m * 16384)
                             : (W2 + (size_t)(m - 4) * 16384);
    float4 v = *(const float4*)(W + (size_t)k * 128 + n4);
    __half* dst = g_wh + (size_t)m * 16384;
    dst[(n4 + 0) * 128 + k] = __float2half_rn(v.x);
    dst[(n4 + 1) * 128 + k] = __float2half_rn(v.y);
    dst[(n4 + 2) * 128 + k] = __float2half_rn(v.z);
    dst[(n4 + 3) * 128 + k] = __float2half_rn(v.w);
}

// ---------------- aggregation: fp16 rows, fp32 accumulate, fp16 out ----------------
__global__ void gather_k() {
    int w = (blockIdx.x * blockDim.x + threadIdx.x) >> 5;
    int lane = threadIdx.x & 31;
    if (w >= N_NODES) return;
    const uint2* __restrict__ X = (const uint2*)g_xh;
    float4 a = h4f(__ldg(&X[(size_t)w * 32 + lane]));
    int s = g_off[w];
    int e = s + g_deg[w];
    int k = s;
    for (; k + 8 <= e; k += 8) {
        int j0 = __ldg(&g_csr[k + 0]);
        int j1 = __ldg(&g_csr[k + 1]);
        int j2 = __ldg(&g_csr[k + 2]);
        int j3 = __ldg(&g_csr[k + 3]);
        int j4 = __ldg(&g_csr[k + 4]);
        int j5 = __ldg(&g_csr[k + 5]);
        int j6 = __ldg(&g_csr[k + 6]);
        int j7 = __ldg(&g_csr[k + 7]);
        float4 v0 = h4f(__ldg(&X[(size_t)j0 * 32 + lane]));
        float4 v1 = h4f(__ldg(&X[(size_t)j1 * 32 + lane]));
        float4 v2 = h4f(__ldg(&X[(size_t)j2 * 32 + lane]));
        float4 v3 = h4f(__ldg(&X[(size_t)j3 * 32 + lane]));
        float4 v4 = h4f(__ldg(&X[(size_t)j4 * 32 + lane]));
        float4 v5 = h4f(__ldg(&X[(size_t)j5 * 32 + lane]));
        float4 v6 = h4f(__ldg(&X[(size_t)j6 * 32 + lane]));
        float4 v7 = h4f(__ldg(&X[(size_t)j7 * 32 + lane]));
        a.x += ((v0.x + v1.x) + (v2.x + v3.x)) + ((v4.x + v5.x) + (v6.x + v7.x));
        a.y += ((v0.y + v1.y) + (v2.y + v3.y)) + ((v4.y + v5.y) + (v6.y + v7.y));
        a.z += ((v0.z + v1.z) + (v2.z + v3.z)) + ((v4.z + v5.z) + (v6.z + v7.z));
        a.w += ((v0.w + v1.w) + (v2.w + v3.w)) + ((v4.w + v5.w) + (v6.w + v7.w));
    }
    for (; k < e; k++) {
        int j = __ldg(&g_csr[k]);
        float4 v = h4f(__ldg(&X[(size_t)j * 32 + lane]));
        a.x += v.x; a.y += v.y; a.z += v.z; a.w += v.w;
    }
    __half2 h0 = __floats2half2_rn(a.x, a.y);
    __half2 h1 = __floats2half2_rn(a.z, a.w);
    uint2 u;
    u.x = *(uint32_t*)&h0;
    u.y = *(uint32_t*)&h1;
    ((uint2*)g_agg)[(size_t)w * 32 + lane] = u;
}

// ---------------- GEMM kernel (mma.sync m16n8k16 fp16), 64-row tiles ----------------
// mode 0: g_h = fp16(relu(g_agg @ W + bias))
// mode 1: out = resid + relu(g_h @ W + bias);  also writes fp16 mirror g_xh
// 256 threads = 8 warps as 2(m) x 4(n); each warp 32m x 32n.
// smem: bias fp32 (512B) | sA half[64][136] (17408B) | sW half[128][136] (34816B)
#define SH_STRIDE 136                      // halves; conflict-free frag LDS
#define SMEM_BYTES (1024 + 64 * SH_STRIDE * 2 + 128 * SH_STRIDE * 2)  // 53248

__device__ __forceinline__ void mmaf16(float* d, const uint32_t* a, const uint32_t* b) {
    asm volatile(
        "mma.sync.aligned.m16n8k16.row.col.f32.f16.f16.f32 "
        "{%0,%1,%2,%3}, {%4,%5,%6,%7}, {%8,%9}, {%0,%1,%2,%3};\n"
        : "+f"(d[0]), "+f"(d[1]), "+f"(d[2]), "+f"(d[3])
        : "r"(a[0]), "r"(a[1]), "r"(a[2]), "r"(a[3]), "r"(b[0]), "r"(b[1]));
}

__global__ __launch_bounds__(256, 3)
void gemm_k(int wsel, const float* __restrict__ bias,
            const float* __restrict__ resid, float* __restrict__ out_arg,
            int mode)
{
    const __half* __restrict__ A  = (mode == 0) ? g_agg : g_h;
    const __half* __restrict__ Wt = g_wh + (size_t)wsel * 16384;  // [n][k]

    extern __shared__ char smc[];
    float*  sbias = (float*)smc;
    __half* sA = (__half*)(smc + 1024);
    __half* sW = (__half*)(smc + 1024 + 64 * SH_STRIDE * 2);

    int tid = threadIdx.x, wid = tid >> 5, lane = tid & 31;
    int bm = blockIdx.x * 64;

    if (tid < 128) sbias[tid] = bias[tid];

    // ---- load Wt tile (128n x 128k halves) ----
    {
        const uint4* W4 = (const uint4*)Wt;     // 16 uint4 per row
#pragma unroll
        for (int it = 0; it < 8; it++) {
            int idx = it * 256 + tid;           // 0..2047
            int n = idx >> 4, c8 = (idx & 15) * 8;
            *(uint4*)&sW[n * SH_STRIDE + c8] = W4[idx];
        }
    }
    // ---- load A tile (64m x 128k halves) ----
    {
        const uint4* A4 = (const uint4*)A;
#pragma unroll
        for (int it = 0; it < 4; it++) {
            int idx = it * 256 + tid;           // 0..1023
            int row = idx >> 4, c8 = (idx & 15) * 8;
            uint4 v = make_uint4(0, 0, 0, 0);
            if (bm + row < N_NODES) v = A4[(size_t)(bm + row) * 16 + (c8 >> 3)];
            *(uint4*)&sA[row * SH_STRIDE + c8] = v;
        }
    }
    __syncthreads();

    int m_base = (wid & 1) * 32;
    int n_base = (wid >> 1) * 32;
    int qr = lane >> 2;
    int qc = lane & 3;

    float acc[2][4][4];
#pragma unroll
    for (int mt = 0; mt < 2; mt++)
#pragma unroll
        for (int nt = 0; nt < 4; nt++)
#pragma unroll
            for (int j = 0; j < 4; j++) acc[mt][nt][j] = 0.f;

#pragma unroll
    for (int ks = 0; ks < 8; ks++) {
        int k = ks * 16;
        uint32_t afr[2][4];
#pragma unroll
        for (int mt = 0; mt < 2; mt++) {
            const __half* ar = &sA[(m_base + mt * 16 + qr) * SH_STRIDE + k + 2 * qc];
            afr[mt][0] = *(const uint32_t*)ar;                      // (qr,   k+2qc)
            afr[mt][1] = *(const uint32_t*)(ar + 8 * SH_STRIDE);    // (qr+8, k+2qc)
            afr[mt][2] = *(const uint32_t*)(ar + 8);                // (qr,   k+2qc+8)
            afr[mt][3] = *(const uint32_t*)(ar + 8 * SH_STRIDE + 8);
        }
        uint32_t bfr[4][2];
#pragma unroll
        for (int nt = 0; nt < 4; nt++) {
            const __half* br = &sW[(n_base + nt * 8 + qr) * SH_STRIDE + k + 2 * qc];
            bfr[nt][0] = *(const uint32_t*)br;        // B[k+2qc..+1][n=qr]
            bfr[nt][1] = *(const uint32_t*)(br + 8);  // B[k+2qc+8..][n=qr]
        }
#pragma unroll
        for (int mt = 0; mt < 2; mt++)
#pragma unroll
            for (int nt = 0; nt < 4; nt++)
                mmaf16(acc[mt][nt], afr[mt], bfr[nt]);
    }

    // ---- epilogue ----
    if (mode == 0) {
#pragma unroll
        for (int mt = 0; mt < 2; mt++) {
#pragma unroll
            for (int h2 = 0; h2 < 2; h2++) {
                int r = bm + m_base + mt * 16 + qr + h2 * 8;
                if (r >= N_NODES) continue;
#pragma unroll
                for (int nt = 0; nt < 4; nt++) {
                    int c = n_base + nt * 8 + qc * 2;
                    float vx = fmaxf(acc[mt][nt][h2 * 2 + 0] + sbias[c], 0.f);
                    float vy = fmaxf(acc[mt][nt][h2 * 2 + 1] + sbias[c + 1], 0.f);
                    __half2 hh = __floats2half2_rn(vx, vy);
                    *(__half2*)&g_h[(size_t)r * 128 + c] = hh;
                }
            }
        }
    } else {
#pragma unroll
        for (int mt = 0; mt < 2; mt++) {
#pragma unroll
            for (int h2 = 0; h2 < 2; h2++) {
                int r = bm + m_base + mt * 16 + qr + h2 * 8;
                if (r >= N_NODES) continue;
#pragma unroll
                for (int nt = 0; nt < 4; nt++) {
                    int c = n_base + nt * 8 + qc * 2;
                    float2 rv = *(const float2*)(resid + (size_t)r * 128 + c);
                    float2 o;
                    o.x = rv.x + fmaxf(acc[mt][nt][h2 * 2 + 0] + sbias[c], 0.f);
                    o.y = rv.y + fmaxf(acc[mt][nt][h2 * 2 + 1] + sbias[c + 1], 0.f);
                    *(float2*)(out_arg + (size_t)r * 128 + c) = o;
                    __half2 hh = __floats2half2_rn(o.x, o.y);
                    *(__half2*)&g_xh[(size_t)r * 128 + c] = hh;
                }
            }
        }
    }
}

// ---------------- launch ----------------
extern "C" void kernel_launch(void* const* d_in, const int* in_sizes, int n_in,
                              void* d_out, int out_size) {
    const float* x0  = (const float*)d_in[0];
    const void*  ei  = d_in[1];
    const float* W1  = (const float*)d_in[2];
    const float* b1  = (const float*)d_in[3];
    const float* W2  = (const float*)d_in[4];
    const float* b2  = (const float*)d_in[5];
    float*       xout = (float*)d_out;

    static int smem_set = 0;
    if (!smem_set) {
        cudaFuncSetAttribute(gemm_k, cudaFuncAttributeMaxDynamicSharedMemorySize,
                             SMEM_BYTES);
        smem_set = 1;
    }

    detect_k<<<1, 32>>>(ei);
    zero_deg_k<<<(N_NODES + 255) / 256, 256>>>();
    count_k<<<(N_EDGES + 255) / 256, 256>>>(ei);
    int nb = (N_NODES + 1023) / 1024;
    scan1_k<<<nb, 1024>>>();
    scan2_k<<<1, 128>>>(nb);
    scan3_k<<<(N_NODES + 255) / 256, 256>>>();
    fill_k<<<(N_EDGES + 255) / 256, 256>>>(ei);
    tohalf_k<<<(N_NODES * 32 + 255) / 256, 256>>>(x0);
    convw_k<<<(8 * 128 * 32 + 255) / 256, 256>>>(W1, W2);

    int ggrid = (N_NODES + 63) / 64;     // 1563
    for (int l = 0; l < 4; l++) {
        const float* xin = (l == 0) ? x0 : xout;
        gather_k<<<(N_NODES + 7) / 8, 256>>>();
        gemm_k<<<ggrid, 256, SMEM_BYTES>>>(l, b1 + (size_t)l * HID,
                                           nullptr, nullptr, 0);
        gemm_k<<<ggrid, 256, SMEM_BYTES>>>(4 + l, b2 + (size_t)l * HID,
                                           xin, xout, 1);
    }
}

// round 12
// speedup vs baseline: 1.4293x; 1.0882x over previous
#include <cuda_runtime.h>
#include <cuda_fp16.h>
#include <cstdint>

#define N_NODES 100000
#define N_EDGES 1600000
#define HID 128

// ---------------- device scratch ----------------
__device__ int g_deg[N_NODES];
__device__ int g_off[N_NODES];
__device__ int g_cur[N_NODES];
__device__ int g_bsum[128];
__device__ int g_csr[N_EDGES];
__device__ int g_e32;
__device__ __half g_agg[(size_t)N_NODES * HID];  // gather output (fp16)
__device__ __half g_xh[(size_t)N_NODES * HID];   // fp16 mirror of current x
__device__ __half g_wh[8 * 128 * 128];           // fp16 TRANSPOSED weights Wt[n][k]

// ---------------- edge dtype detection ----------------
__global__ void detect_k(const void* __restrict__ ei) {
    if (threadIdx.x == 0 && blockIdx.x == 0) {
        const long long* p = (const long long*)ei;
        int e32 = 0;
        for (int i = 0; i < 16; i++) {
            long long v = p[i];
            if (v < 0 || v >= N_NODES) { e32 = 1; break; }
        }
        g_e32 = e32;
    }
}
__device__ __forceinline__ int edge_at(const void* ei, long long idx) {
    if (g_e32) return ((const int*)ei)[idx];
    return (int)((const long long*)ei)[idx];
}

// ---------------- CSR build ----------------
__global__ void zero_deg_k() {
    int i = blockIdx.x * blockDim.x + threadIdx.x;
    if (i < N_NODES) g_deg[i] = 0;
}
__global__ void count_k(const void* __restrict__ ei) {
    int e = blockIdx.x * blockDim.x + threadIdx.x;
    if (e < N_EDGES) {
        int d = edge_at(ei, (long long)N_EDGES + e);
        if (d >= 0 && d < N_NODES) atomicAdd(&g_deg[d], 1);
    }
}
__global__ void scan1_k() {
    __shared__ int s[1024];
    int t = threadIdx.x;
    int i = blockIdx.x * 1024 + t;
    int v = (i < N_NODES) ? g_deg[i] : 0;
    s[t] = v;
    __syncthreads();
    for (int o = 1; o < 1024; o <<= 1) {
        int x = (t >= o) ? s[t - o] : 0;
        __syncthreads();
        s[t] += x;
        __syncthreads();
    }
    if (i < N_NODES) g_off[i] = s[t] - v;
    if (t == 1023) g_bsum[blockIdx.x] = s[1023];
}
__global__ void scan2_k(int nb) {
    __shared__ int s[128];
    int t = threadIdx.x;
    int v = (t < nb) ? g_bsum[t] : 0;
    s[t] = v;
    __syncthreads();
    for (int o = 1; o < 128; o <<= 1) {
        int x = (t >= o) ? s[t - o] : 0;
        __syncthreads();
        s[t] += x;
        __syncthreads();
    }
    if (t < nb) g_bsum[t] = s[t] - v;
}
__global__ void scan3_k() {
    int i = blockIdx.x * blockDim.x + threadIdx.x;
    if (i < N_NODES) {
        int o = g_off[i] + g_bsum[i >> 10];
        g_off[i] = o;
        g_cur[i] = o;
    }
}
__global__ void fill_k(const void* __restrict__ ei) {
    int e = blockIdx.x * blockDim.x + threadIdx.x;
    if (e < N_EDGES) {
        int d = edge_at(ei, (long long)N_EDGES + e);
        int s = edge_at(ei, e);
        if (d < 0 || d >= N_NODES) return;
        if (s < 0) s = 0;
        if (s >= N_NODES) s = N_NODES - 1;
        int p = atomicAdd(&g_cur[d], 1);
        if (p >= 0 && p < N_EDGES) g_csr[p] = s;
    }
}

// ---------------- one-time converts ----------------
__global__ void tohalf_k(const float* __restrict__ x) {
    int i = blockIdx.x * blockDim.x + threadIdx.x;   // float4 index
    if (i < N_NODES * 32) {
        float4 v = ((const float4*)x)[i];
        __half2 h0 = __floats2half2_rn(v.x, v.y);
        __half2 h1 = __floats2half2_rn(v.z, v.w);
        uint2 u;
        u.x = *(uint32_t*)&h0;
        u.y = *(uint32_t*)&h1;
        ((uint2*)g_xh)[i] = u;
    }
}

// convert + transpose all 8 weight matrices: g_wh[m][n][k] = fp16(W[m][k][n])
__global__ void convw_k(const float* __restrict__ W1, const float* __restrict__ W2) {
    int i = blockIdx.x * blockDim.x + threadIdx.x;   // 8*128*32
    if (i >= 8 * 128 * 32) return;
    int n4 = (i & 31) * 4;
    int k  = (i >> 5) & 127;
    int m  = i >> 12;
    const float* W = (m < 4) ? (W1 + (size_t)m * 16384)
                             : (W2 + (size_t)(m - 4) * 16384);
    float4 v = *(const float4*)(W + (size_t)k * 128 + n4);
    __half* dst = g_wh + (size_t)m * 16384;
    dst[(n4 + 0) * 128 + k] = __float2half_rn(v.x);
    dst[(n4 + 1) * 128 + k] = __float2half_rn(v.y);
    dst[(n4 + 2) * 128 + k] = __float2half_rn(v.z);
    dst[(n4 + 3) * 128 + k] = __float2half_rn(v.w);
}

// ---------------- gather: half-warp per row (2 rows per warp-load) ----------------
// One warp per node. Lanes 0-15 (half 0) process edges s, s+2, ...;
// lanes 16-31 (half 1) process s+1, s+3, ... Each half-warp reads a full
// 256B fp16 row via 16 x LDG.128. Partial sums combined via shfl_xor(16).
__device__ __forceinline__ void acc8(float* a, uint4 r) {
    __half2* hp = (__half2*)&r;
    float2 f0 = __half22float2(hp[0]);
    float2 f1 = __half22float2(hp[1]);
    float2 f2 = __half22float2(hp[2]);
    float2 f3 = __half22float2(hp[3]);
    a[0] += f0.x; a[1] += f0.y; a[2] += f1.x; a[3] += f1.y;
    a[4] += f2.x; a[5] += f2.y; a[6] += f3.x; a[7] += f3.y;
}

__global__ __launch_bounds__(256) void gather_k() {
    int w = (blockIdx.x * blockDim.x + threadIdx.x) >> 5;
    int lane = threadIdx.x & 31;
    if (w >= N_NODES) return;
    int half = lane >> 4;      // 0 or 1
    int sl   = lane & 15;      // 0..15: 16B chunk within row
    const uint4* __restrict__ X = (const uint4*)g_xh;   // 16 uint4 per row

    float a[8];
    {
        uint4 self = __ldg(&X[(size_t)w * 16 + sl]);
#pragma unroll
        for (int f = 0; f < 8; f++) a[f] = 0.f;
        if (half == 0) acc8(a, self);    // self counted once
    }

    int s = g_off[w];
    int e = s + g_deg[w];
    int kb = s;
    for (; kb + 16 <= e; kb += 16) {
        int jj[8];
#pragma unroll
        for (int i = 0; i < 8; i++) jj[i] = __ldg(&g_csr[kb + 2 * i + half]);
        uint4 rr[8];
#pragma unroll
        for (int i = 0; i < 8; i++) rr[i] = __ldg(&X[(size_t)jj[i] * 16 + sl]);
#pragma unroll
        for (int i = 0; i < 8; i++) acc8(a, rr[i]);
    }
    // tail (< 16 edges), warp-uniform control with per-half predicate
#pragma unroll
    for (int off = 0; off < 16; off += 2) {
        int k = kb + off + half;
        if (k < e) {
            int j = __ldg(&g_csr[k]);
            uint4 r = __ldg(&X[(size_t)j * 16 + sl]);
            acc8(a, r);
        }
    }
    // combine the two half-warps (same features, different edges)
#pragma unroll
    for (int f = 0; f < 8; f++)
        a[f] += __shfl_xor_sync(0xffffffffu, a[f], 16);

    if (half == 0) {
        __half2 h0 = __floats2half2_rn(a[0], a[1]);
        __half2 h1 = __floats2half2_rn(a[2], a[3]);
        __half2 h2 = __floats2half2_rn(a[4], a[5]);
        __half2 h3 = __floats2half2_rn(a[6], a[7]);
        uint4 u;
        u.x = *(uint32_t*)&h0; u.y = *(uint32_t*)&h1;
        u.z = *(uint32_t*)&h2; u.w = *(uint32_t*)&h3;
        ((uint4*)g_agg)[(size_t)w * 16 + sl] = u;
    }
}

// ---------------- fused 2-GEMM MLP (mma.sync m16n8k16 fp16) ----------------
// One CTA = 128 node rows, both GEMMs; h lives in smem.
//   pass0: h = fp16(relu(sA @ W1 + b1)) -> overwrite sA
//   pass1: out = resid + relu(sA @ W2 + b2); fp32 out + fp16 mirror
// 256 threads = 8 warps as 4(m) x 2(n); warp tile 32m x 64n.
#define FSH 136   // halves per smem row; conflict-free frag LDS
#define SMB_B1 0
#define SMB_B2 512
#define SMB_A  1024
#define SMB_W1 (SMB_A  + 128 * FSH * 2)   // 1024 + 34816
#define SMB_W2 (SMB_W1 + 128 * FSH * 2)
#define SMEM_BYTES (SMB_W2 + 128 * FSH * 2)   // 105472

__device__ __forceinline__ void mmaf16(float* d, const uint32_t* a, const uint32_t* b) {
    asm volatile(
        "mma.sync.aligned.m16n8k16.row.col.f32.f16.f16.f32 "
        "{%0,%1,%2,%3}, {%4,%5,%6,%7}, {%8,%9}, {%0,%1,%2,%3};\n"
        : "+f"(d[0]), "+f"(d[1]), "+f"(d[2]), "+f"(d[3])
        : "r"(a[0]), "r"(a[1]), "r"(a[2]), "r"(a[3]), "r"(b[0]), "r"(b[1]));
}

__global__ __launch_bounds__(256, 2)
void mlp_k(int l, const float* __restrict__ b1, const float* __restrict__ b2,
           const float* __restrict__ resid, float* __restrict__ out)
{
    const __half* __restrict__ Wt1 = g_wh + (size_t)l * 16384;
    const __half* __restrict__ Wt2 = g_wh + (size_t)(4 + l) * 16384;

    extern __shared__ char smc[];
    float*  sb1 = (float*)(smc + SMB_B1);
    float*  sb2 = (float*)(smc + SMB_B2);
    __half* sA  = (__half*)(smc + SMB_A);
    __half* sW1 = (__half*)(smc + SMB_W1);
    __half* sW2 = (__half*)(smc + SMB_W2);

    int tid = threadIdx.x, wid = tid >> 5, lane = tid & 31;
    int bm = blockIdx.x * 128;

    if (tid < 128) { sb1[tid] = b1[tid]; sb2[tid] = b2[tid]; }

    // ---- load W1t, W2t (128n x 128k halves each) ----
    {
        const uint4* W41 = (const uint4*)Wt1;
        const uint4* W42 = (const uint4*)Wt2;
#pragma unroll
        for (int it = 0; it < 8; it++) {
            int idx = it * 256 + tid;          // 0..2047
            int n = idx >> 4, c8 = (idx & 15) * 8;
            *(uint4*)&sW1[n * FSH + c8] = W41[idx];
            *(uint4*)&sW2[n * FSH + c8] = W42[idx];
        }
    }
    // ---- load A tile (128m x 128k halves) from g_agg ----
    {
        const uint4* A4 = (const uint4*)g_agg;
#pragma unroll
        for (int it = 0; it < 8; it++) {
            int idx = it * 256 + tid;          // 0..2047
            int row = idx >> 4, c8 = (idx & 15) * 8;
            uint4 v = make_uint4(0, 0, 0, 0);
            if (bm + row < N_NODES) v = A4[(size_t)(bm + row) * 16 + (c8 >> 3)];
            *(uint4*)&sA[row * FSH + c8] = v;
        }
    }
    __syncthreads();

    int m_base = (wid & 3) * 32;    // 4 m-groups
    int n_base = (wid >> 2) * 64;   // 2 n-groups
    int qr = lane >> 2;
    int qc = lane & 3;

    float acc[2][8][4];

#pragma unroll 1
    for (int pass = 0; pass < 2; pass++) {
        const __half* sW = (pass == 0) ? sW1 : sW2;
#pragma unroll
        for (int mt = 0; mt < 2; mt++)
#pragma unroll
            for (int nt = 0; nt < 8; nt++)
#pragma unroll
                for (int j = 0; j < 4; j++) acc[mt][nt][j] = 0.f;

#pragma unroll
        for (int ks = 0; ks < 8; ks++) {
            int k = ks * 16;
            uint32_t afr[2][4];
#pragma unroll
            for (int mt = 0; mt < 2; mt++) {
                const __half* ar = &sA[(m_base + mt * 16 + qr) * FSH + k + 2 * qc];
                afr[mt][0] = *(const uint32_t*)ar;
                afr[mt][1] = *(const uint32_t*)(ar + 8 * FSH);
                afr[mt][2] = *(const uint32_t*)(ar + 8);
                afr[mt][3] = *(const uint32_t*)(ar + 8 * FSH + 8);
            }
            uint32_t bfr[8][2];
#pragma unroll
            for (int nt = 0; nt < 8; nt++) {
                const __half* br = &sW[(n_base + nt * 8 + qr) * FSH + k + 2 * qc];
                bfr[nt][0] = *(const uint32_t*)br;
                bfr[nt][1] = *(const uint32_t*)(br + 8);
            }
#pragma unroll
            for (int mt = 0; mt < 2; mt++)
#pragma unroll
                for (int nt = 0; nt < 8; nt++)
                    mmaf16(acc[mt][nt], afr[mt], bfr[nt]);
        }

        if (pass == 0) {
            // epilogue 1: h = fp16(relu(acc + b1)) -> back into sA
            __syncthreads();   // all frag reads done before overwrite
#pragma unroll
            for (int mt = 0; mt < 2; mt++) {
#pragma unroll
                for (int h2 = 0; h2 < 2; h2++) {
                    int r0 = m_base + mt * 16 + qr + h2 * 8;
#pragma unroll
                    for (int nt = 0; nt < 8; nt++) {
                        int c = n_base + nt * 8 + qc * 2;
                        float vx = fmaxf(acc[mt][nt][h2 * 2 + 0] + sb1[c], 0.f);
                        float vy = fmaxf(acc[mt][nt][h2 * 2 + 1] + sb1[c + 1], 0.f);
                        *(__half2*)&sA[r0 * FSH + c] = __floats2half2_rn(vx, vy);
                    }
                }
            }
            __syncthreads();
        }
    }

    // epilogue 2: out = resid + relu(acc + b2); fp32 + fp16 mirror
#pragma unroll
    for (int mt = 0; mt < 2; mt++) {
#pragma unroll
        for (int h2 = 0; h2 < 2; h2++) {
            int r = bm + m_base + mt * 16 + qr + h2 * 8;
            if (r >= N_NODES) continue;
#pragma unroll
            for (int nt = 0; nt < 8; nt++) {
                int c = n_base + nt * 8 + qc * 2;
                float2 rv = *(const float2*)(resid + (size_t)r * 128 + c);
                float2 o;
                o.x = rv.x + fmaxf(acc[mt][nt][h2 * 2 + 0] + sb2[c], 0.f);
                o.y = rv.y + fmaxf(acc[mt][nt][h2 * 2 + 1] + sb2[c + 1], 0.f);
                *(float2*)(out + (size_t)r * 128 + c) = o;
                *(__half2*)&g_xh[(size_t)r * 128 + c] = __floats2half2_rn(o.x, o.y);
            }
        }
    }
}

// ---------------- launch ----------------
extern "C" void kernel_launch(void* const* d_in, const int* in_sizes, int n_in,
                              void* d_out, int out_size) {
    const float* x0  = (const float*)d_in[0];
    const void*  ei  = d_in[1];
    const float* W1  = (const float*)d_in[2];
    const float* b1  = (const float*)d_in[3];
    const float* W2  = (const float*)d_in[4];
    const float* b2  = (const float*)d_in[5];
    float*       xout = (float*)d_out;

    static int smem_set = 0;
    if (!smem_set) {
        cudaFuncSetAttribute(mlp_k, cudaFuncAttributeMaxDynamicSharedMemorySize,
                             SMEM_BYTES);
        smem_set = 1;
    }

    detect_k<<<1, 32>>>(ei);
    zero_deg_k<<<(N_NODES + 255) / 256, 256>>>();
    count_k<<<(N_EDGES + 255) / 256, 256>>>(ei);
    int nb = (N_NODES + 1023) / 1024;
    scan1_k<<<nb, 1024>>>();
    scan2_k<<<1, 128>>>(nb);
    scan3_k<<<(N_NODES + 255) / 256, 256>>>();
    fill_k<<<(N_EDGES + 255) / 256, 256>>>(ei);
    tohalf_k<<<(N_NODES * 32 + 255) / 256, 256>>>(x0);
    convw_k<<<(8 * 128 * 32 + 255) / 256, 256>>>(W1, W2);

    int mgrid = (N_NODES + 127) / 128;   // 782
    for (int l = 0; l < 4; l++) {
        const float* xin = (l == 0) ? x0 : xout;
        gather_k<<<(N_NODES + 7) / 8, 256>>>();
        mlp_k<<<mgrid, 256, SMEM_BYTES>>>(l, b1 + (size_t)l * HID,
                                          b2 + (size_t)l * HID, xin, xout);
    }
}